// round 14
// baseline (speedup 1.0000x reference)
#include <cuda_runtime.h>
#include <cuda_bf16.h>
#include <float.h>
#include <stdint.h>

#define BQ 8
#define NP 2048
#define KNN 20
#define MROWS (BQ*NP)        // 16384
#define EPSBN 1e-5f
#define TCAP 192

// ------------------------- device scratch (global) --------------------------
__device__ float g_XT[MROWS*16];
__device__ float g_cat[(size_t)MROWS*512];
__device__ float g_U[(size_t)MROWS*512];
__device__ float g_Y[(size_t)MROWS*1024];
__device__ float g_D[(size_t)MROWS*NP];
__device__ float g_xx[MROWS];
__device__ int   g_idx[MROWS*KNN];
__device__ float g_Wc[512*512];
__device__ float g_part1[1024*1024];
__device__ float g_part2[1024*1024];
__device__ float g_pchunk[8*BQ*1024];
__device__ float g_sum[1024];
__device__ float g_sumsq[1024];
__device__ float g_scale[1024];
__device__ float g_shift[1024];
__device__ float g_P[BQ*2048];
__device__ float g_h1[BQ*512];
__device__ float g_h2[BQ*256];
__device__ unsigned int g_pmax[BQ*1024];

// ------------------------------ helpers -------------------------------------

__device__ __forceinline__ unsigned int fenc(float v) {
    unsigned int b = __float_as_uint(v);
    return (b & 0x80000000u) ? ~b : (b | 0x80000000u);
}
__device__ __forceinline__ float fdec(unsigned int u) {
    unsigned int b = (u & 0x80000000u) ? (u ^ 0x80000000u) : ~u;
    return __uint_as_float(b);
}

__device__ __forceinline__ void tile_store(float* S, int f, float4 v)
{
    int m  = f >> 2;
    int kq = f & 3;
    int col = m ^ (kq << 3);
    S[(4*kq + 0)*128 + col] = v.x;
    S[(4*kq + 1)*128 + col] = v.y;
    S[(4*kq + 2)*128 + col] = v.z;
    S[(4*kq + 3)*128 + col] = v.w;
}

// ------------------------------- kernels ------------------------------------

__global__ void k_transpose_pad(const float* __restrict__ x, float* __restrict__ XT)
{
    int i = blockIdx.x * blockDim.x + threadIdx.x;
    if (i >= MROWS) return;
    int b = i >> 11, n = i & (NP-1);
    float v0 = x[(b*3 + 0)*NP + n];
    float v1 = x[(b*3 + 1)*NP + n];
    float v2 = x[(b*3 + 2)*NP + n];
    float4* o = (float4*)(XT + (size_t)i*16);
    o[0] = make_float4(v0, v1, v2, 0.f);
    o[1] = make_float4(0.f, 0.f, 0.f, 0.f);
    o[2] = make_float4(0.f, 0.f, 0.f, 0.f);
    o[3] = make_float4(0.f, 0.f, 0.f, 0.f);
}

__global__ void k_sqnorm(const float* __restrict__ X, int ldx, int xoff, int C,
                         float* __restrict__ xx)
{
    int r = blockIdx.x * blockDim.x + threadIdx.x;
    if (r >= MROWS) return;
    const float* p = X + (size_t)r*ldx + xoff;
    float s = 0.f;
    for (int c = 0; c < C; ++c) { float v = p[c]; s += v*v; }
    xx[r] = s;
}

// Symmetric pairwise distance: upper-tri tiles + smem-staged coalesced mirror.
__global__ void __launch_bounds__(256, 2)
k_dist_sym(const float* __restrict__ X, int ldx, int xoff,
           const float* __restrict__ xx, float* __restrict__ D, int Kd)
{
    __shared__ __align__(16) char smraw[32*132*4];   // 16.9 KB, unions As/Bs
    float* As = (float*)smraw;                        // 16*128 floats
    float* Bs = As + 16*128;                          // needs 16 KB total
    float* Tr = (float*)smraw;                        // 32x132 transpose buffer

    int b = blockIdx.z;
    int li = blockIdx.x;
    int ti = 0;
    while (li >= 16 - ti) { li -= 16 - ti; ++ti; }
    int tj = ti + li;
    int n0 = ti * 128;
    int m0 = tj * 128;
    size_t base = (size_t)b * NP;
    int t  = threadIdx.x;
    int tx = t & 15, ty = t >> 4;

    float acc[8][8] = {};
    int f0 = t, f1 = t + 256;
    float4 pa0 = *(const float4*)(X + (base + n0 + (f0>>2))*(size_t)ldx + xoff + (f0&3)*4);
    float4 pa1 = *(const float4*)(X + (base + n0 + (f1>>2))*(size_t)ldx + xoff + (f1&3)*4);
    float4 pb0 = *(const float4*)(X + (base + m0 + (f0>>2))*(size_t)ldx + xoff + (f0&3)*4);
    float4 pb1 = *(const float4*)(X + (base + m0 + (f1>>2))*(size_t)ldx + xoff + (f1&3)*4);

    for (int k0 = 0; k0 < Kd; k0 += 16) {
        tile_store(As, f0, pa0);
        tile_store(As, f1, pa1);
        tile_store(Bs, f0, pb0);
        tile_store(Bs, f1, pb1);
        __syncthreads();
        if (k0 + 16 < Kd) {
            int kn = k0 + 16;
            pa0 = *(const float4*)(X + (base + n0 + (f0>>2))*(size_t)ldx + xoff + kn + (f0&3)*4);
            pa1 = *(const float4*)(X + (base + n0 + (f1>>2))*(size_t)ldx + xoff + kn + (f1&3)*4);
            pb0 = *(const float4*)(X + (base + m0 + (f0>>2))*(size_t)ldx + xoff + kn + (f0&3)*4);
            pb1 = *(const float4*)(X + (base + m0 + (f1>>2))*(size_t)ldx + xoff + kn + (f1&3)*4);
        }
#pragma unroll
        for (int kk = 0; kk < 16; ++kk) {
            int swz = (kk >> 2) << 3;
            const float4* pa = (const float4*)&As[kk*128 + ((ty*8) ^ swz)];
            const float4* pb = (const float4*)&Bs[kk*128 + ((tx*8) ^ swz)];
            float4 a03 = pa[0], a47 = pa[1];
            float4 b03 = pb[0], b47 = pb[1];
            float a_[8] = {a03.x,a03.y,a03.z,a03.w,a47.x,a47.y,a47.z,a47.w};
            float b_[8] = {b03.x,b03.y,b03.z,b03.w,b47.x,b47.y,b47.z,b47.w};
#pragma unroll
            for (int i = 0; i < 8; ++i)
#pragma unroll
                for (int j = 0; j < 8; ++j) acc[i][j] += a_[i]*b_[j];
        }
        __syncthreads();
    }
    float xm[8];
#pragma unroll
    for (int j = 0; j < 8; ++j) xm[j] = xx[base + m0 + tx*8 + j];
#pragma unroll
    for (int i = 0; i < 8; ++i) {
        float xn = xx[base + n0 + ty*8 + i];
#pragma unroll
        for (int j = 0; j < 8; ++j) acc[i][j] = 2.f*acc[i][j] - xn - xm[j];
    }
    // normal tile write (coalesced)
#pragma unroll
    for (int i = 0; i < 8; ++i) {
        float* dp = D + (base + n0 + ty*8 + i)*(size_t)NP + m0 + tx*8;
        ((float4*)dp)[0] = make_float4(acc[i][0], acc[i][1], acc[i][2], acc[i][3]);
        ((float4*)dp)[1] = make_float4(acc[i][4], acc[i][5], acc[i][6], acc[i][7]);
    }
    // mirror tile: stage 32-row chunks through smem, write coalesced
    if (m0 != n0) {
#pragma unroll 1
        for (int c = 0; c < 4; ++c) {
            __syncthreads();
            if ((tx >> 2) == c) {
                int r0 = (tx & 3) * 8;      // local row base within chunk
#pragma unroll
                for (int j = 0; j < 8; ++j)
#pragma unroll
                    for (int i = 0; i < 8; ++i)
                        Tr[(r0 + j)*132 + ty*8 + i] = acc[i][j];
            }
            __syncthreads();
            // 256 threads write 32 rows x 128 floats: 8 threads/row, 4 float4 each
            int lr  = t >> 3;               // 0..31
            int seg = t & 7;                // 0..7
            float* dp = D + (base + m0 + c*32 + lr)*(size_t)NP + n0 + seg*16;
            const float* sp = &Tr[lr*132 + seg*16];
            ((float4*)dp)[0] = *(const float4*)(sp);
            ((float4*)dp)[1] = *(const float4*)(sp + 4);
            ((float4*)dp)[2] = *(const float4*)(sp + 8);
            ((float4*)dp)[3] = *(const float4*)(sp + 12);
        }
    }
}

// ---- warp top-20: lane-max bound pass, then single filtered collect ----
__global__ void __launch_bounds__(256)
k_topk(const float* __restrict__ D, int* __restrict__ idxout)
{
    __shared__ unsigned long long sbuf[8][TCAP];
    __shared__ unsigned long long slist[8][KNN];
    __shared__ int scnt[8];

    int warp = threadIdx.x >> 5, lane = threadIdx.x & 31;
    int row  = blockIdx.x * 8 + warp;
    const float4* drow4 = (const float4*)(D + (size_t)row * NP);

    float lmax = -FLT_MAX;
#pragma unroll
    for (int f = 0; f < 16; ++f) {
        float4 v4 = drow4[f*32 + lane];
        lmax = fmaxf(lmax, fmaxf(fmaxf(v4.x, v4.y), fmaxf(v4.z, v4.w)));
    }
    int rank = 0;
#pragma unroll
    for (int i = 0; i < 32; ++i) {
        float vi = __shfl_sync(0xffffffffu, lmax, i);
        rank += (vi > lmax || (vi == lmax && i < lane)) ? 1 : 0;
    }
    unsigned r19 = __ballot_sync(0xffffffffu, rank == 19);
    float T = __shfl_sync(0xffffffffu, lmax, __ffs(r19) - 1);

    if (lane == 0) scnt[warp] = 0;
    __syncwarp();

#pragma unroll 4
    for (int f = 0; f < 16; ++f) {
        float4 v4 = drow4[f*32 + lane];
        int base = (f*32 + lane)*4;
        unsigned q = 0;
        q |= (v4.x >= T) ? 1u : 0u;
        q |= (v4.y >= T) ? 2u : 0u;
        q |= (v4.z >= T) ? 4u : 0u;
        q |= (v4.w >= T) ? 8u : 0u;
        if (q) {
            float vals[4] = {v4.x, v4.y, v4.z, v4.w};
#pragma unroll 1
            do {
                int e = __ffs(q) - 1;
                q &= q - 1;
                int pos = atomicAdd(&scnt[warp], 1);
                if (pos < TCAP)
                    sbuf[warp][pos] =
                        (((unsigned long long)fenc(vals[e])) << 32)
                        | (unsigned)(NP - 1 - (base + e));
            } while (q);
        }
    }
    __syncwarp();

    if (lane == 0) {
        unsigned long long* L = slist[warp];
#pragma unroll
        for (int i = 0; i < KNN; ++i) L[i] = 0ull;
        int c = scnt[warp];
        if (c <= TCAP) {
            for (int i = 0; i < c; ++i) {
                unsigned long long key = sbuf[warp][i];
                if (key > L[KNN-1]) {
                    int qq = KNN-1;
#pragma unroll 1
                    while (qq > 0 && L[qq-1] < key) { L[qq] = L[qq-1]; --qq; }
                    L[qq] = key;
                }
            }
        } else {
            const float* drow = (const float*)drow4;
            for (int mI = 0; mI < NP; ++mI) {
                unsigned long long key =
                    (((unsigned long long)fenc(drow[mI])) << 32)
                    | (unsigned)(NP - 1 - mI);
                if (key > L[KNN-1]) {
                    int qq = KNN-1;
#pragma unroll 1
                    while (qq > 0 && L[qq-1] < key) { L[qq] = L[qq-1]; --qq; }
                    L[qq] = key;
                }
            }
        }
    }
    __syncwarp();
    if (lane < KNN) {
        unsigned long long key = slist[warp][lane];
        idxout[row*KNN + lane] = NP - 1 - (int)(key & 0xffffffffu);
    }
}

// ---- 128x128x16 fp32 GEMM (conv blocks) ----
__global__ void __launch_bounds__(256, 2)
k_gemm128(const float* __restrict__ A, int lda, int aoff,
          const float* __restrict__ Bw, int ldb,
          float* __restrict__ Cm, int ldc, int coff,
          int Kd)
{
    __shared__ float As[16*128];
    __shared__ float Bs[16*128];
    int n0 = blockIdx.x * 128;
    int m0 = blockIdx.y * 128;
    int t  = threadIdx.x;
    int tx = t & 15, ty = t >> 4;

    float acc[8][8] = {};
    int f0 = t, f1 = t + 256;
    float4 pa0 = *(const float4*)(A  + (size_t)(m0 + (f0>>2))*lda + aoff + (f0&3)*4);
    float4 pa1 = *(const float4*)(A  + (size_t)(m0 + (f1>>2))*lda + aoff + (f1&3)*4);
    float4 pb0 = *(const float4*)(Bw + (size_t)(n0 + (f0>>2))*ldb + (f0&3)*4);
    float4 pb1 = *(const float4*)(Bw + (size_t)(n0 + (f1>>2))*ldb + (f1&3)*4);

    for (int k0 = 0; k0 < Kd; k0 += 16) {
        tile_store(As, f0, pa0);
        tile_store(As, f1, pa1);
        tile_store(Bs, f0, pb0);
        tile_store(Bs, f1, pb1);
        __syncthreads();
        if (k0 + 16 < Kd) {
            int kn = k0 + 16;
            pa0 = *(const float4*)(A  + (size_t)(m0 + (f0>>2))*lda + aoff + kn + (f0&3)*4);
            pa1 = *(const float4*)(A  + (size_t)(m0 + (f1>>2))*lda + aoff + kn + (f1&3)*4);
            pb0 = *(const float4*)(Bw + (size_t)(n0 + (f0>>2))*ldb + kn + (f0&3)*4);
            pb1 = *(const float4*)(Bw + (size_t)(n0 + (f1>>2))*ldb + kn + (f1&3)*4);
        }
#pragma unroll
        for (int kk = 0; kk < 16; ++kk) {
            int swz = (kk >> 2) << 3;
            const float4* pa = (const float4*)&As[kk*128 + ((ty*8) ^ swz)];
            const float4* pb = (const float4*)&Bs[kk*128 + ((tx*8) ^ swz)];
            float4 a03 = pa[0], a47 = pa[1];
            float4 b03 = pb[0], b47 = pb[1];
            float a_[8] = {a03.x,a03.y,a03.z,a03.w,a47.x,a47.y,a47.z,a47.w};
            float b_[8] = {b03.x,b03.y,b03.z,b03.w,b47.x,b47.y,b47.z,b47.w};
#pragma unroll
            for (int i = 0; i < 8; ++i)
#pragma unroll
                for (int j = 0; j < 8; ++j) acc[i][j] += a_[i]*b_[j];
        }
        __syncthreads();
    }
#pragma unroll
    for (int i = 0; i < 8; ++i) {
        float* cp = Cm + (size_t)(m0 + ty*8 + i)*ldc + coff + n0 + tx*8;
        ((float4*)cp)[0] = make_float4(acc[i][0], acc[i][1], acc[i][2], acc[i][3]);
        ((float4*)cp)[1] = make_float4(acc[i][4], acc[i][5], acc[i][6], acc[i][7]);
    }
}

// ---- 128x128x16 fp32 GEMM + deterministic per-column partial stats ----
__global__ void __launch_bounds__(256, 2)
k_gemm128s(const float* __restrict__ A, int lda,
           const float* __restrict__ Bw, int ldb,
           float* __restrict__ Cm, int ldc,
           int Kd, float* __restrict__ part1, float* __restrict__ part2)
{
    __shared__ float As[16*128];
    __shared__ float Bs[16*128];
    int n0 = blockIdx.x * 128;
    int m0 = blockIdx.y * 128;
    int t  = threadIdx.x;
    int tx = t & 15, ty = t >> 4;

    float acc[8][8] = {};
    int f0 = t, f1 = t + 256;
    float4 pa0 = *(const float4*)(A  + (size_t)(m0 + (f0>>2))*lda + (f0&3)*4);
    float4 pa1 = *(const float4*)(A  + (size_t)(m0 + (f1>>2))*lda + (f1&3)*4);
    float4 pb0 = *(const float4*)(Bw + (size_t)(n0 + (f0>>2))*ldb + (f0&3)*4);
    float4 pb1 = *(const float4*)(Bw + (size_t)(n0 + (f1>>2))*ldb + (f1&3)*4);

    for (int k0 = 0; k0 < Kd; k0 += 16) {
        tile_store(As, f0, pa0);
        tile_store(As, f1, pa1);
        tile_store(Bs, f0, pb0);
        tile_store(Bs, f1, pb1);
        __syncthreads();
        if (k0 + 16 < Kd) {
            int kn = k0 + 16;
            pa0 = *(const float4*)(A  + (size_t)(m0 + (f0>>2))*lda + kn + (f0&3)*4);
            pa1 = *(const float4*)(A  + (size_t)(m0 + (f1>>2))*lda + kn + (f1&3)*4);
            pb0 = *(const float4*)(Bw + (size_t)(n0 + (f0>>2))*ldb + kn + (f0&3)*4);
            pb1 = *(const float4*)(Bw + (size_t)(n0 + (f1>>2))*ldb + kn + (f1&3)*4);
        }
#pragma unroll
        for (int kk = 0; kk < 16; ++kk) {
            int swz = (kk >> 2) << 3;
            const float4* pa = (const float4*)&As[kk*128 + ((ty*8) ^ swz)];
            const float4* pb = (const float4*)&Bs[kk*128 + ((tx*8) ^ swz)];
            float4 a03 = pa[0], a47 = pa[1];
            float4 b03 = pb[0], b47 = pb[1];
            float a_[8] = {a03.x,a03.y,a03.z,a03.w,a47.x,a47.y,a47.z,a47.w};
            float b_[8] = {b03.x,b03.y,b03.z,b03.w,b47.x,b47.y,b47.z,b47.w};
#pragma unroll
            for (int i = 0; i < 8; ++i)
#pragma unroll
                for (int j = 0; j < 8; ++j) acc[i][j] += a_[i]*b_[j];
        }
        __syncthreads();
    }
#pragma unroll
    for (int i = 0; i < 8; ++i) {
        float* cp = Cm + (size_t)(m0 + ty*8 + i)*ldc + n0 + tx*8;
        ((float4*)cp)[0] = make_float4(acc[i][0], acc[i][1], acc[i][2], acc[i][3]);
        ((float4*)cp)[1] = make_float4(acc[i][4], acc[i][5], acc[i][6], acc[i][7]);
    }
#pragma unroll
    for (int j = 0; j < 8; ++j) {
        float s0 = 0.f, s1 = 0.f;
#pragma unroll
        for (int i = 0; i < 8; ++i) { float v = acc[i][j]; s0 += v; s1 += v*v; }
        As[ty*128 + tx*8 + j] = s0;
        Bs[ty*128 + tx*8 + j] = s1;
    }
    __syncthreads();
    if (t < 128) {
        float a = 0.f, c2 = 0.f;
#pragma unroll
        for (int g = 0; g < 16; ++g) { a += As[g*128 + t]; c2 += Bs[g*128 + t]; }
        part1[(size_t)blockIdx.y*1024 + n0 + t] = a;
        part2[(size_t)blockIdx.y*1024 + n0 + t] = c2;
    }
}

// deterministic parallel reduction of partials: part[s*stride + o]
__global__ void k_stats_reduce(const float* __restrict__ part1,
                               const float* __restrict__ part2,
                               int nparts, int stride, int O,
                               float* __restrict__ gsum, float* __restrict__ gsq)
{
    __shared__ float s1[8][32], s2[8][32];
    int lane = threadIdx.x & 31;
    int sl   = threadIdx.x >> 5;
    int o    = blockIdx.x * 32 + lane;
    int per  = nparts >> 3;
    float a = 0.f, b = 0.f;
    if (o < O) {
        for (int s = sl*per; s < (sl+1)*per; ++s) {
            a += part1[(size_t)s*stride + o];
            b += part2[(size_t)s*stride + o];
        }
    }
    s1[sl][lane] = a;
    s2[sl][lane] = b;
    __syncthreads();
    if (sl == 0 && o < O) {
        float A = 0.f, B = 0.f;
#pragma unroll
        for (int s = 0; s < 8; ++s) { A += s1[s][lane]; B += s2[s][lane]; }
        gsum[o] = A;
        gsq[o]  = B;
    }
}

__global__ void k_prepw(const float* __restrict__ W, float* __restrict__ Wc,
                        int O, int Creal, int Cpad)
{
    int i = blockIdx.x * blockDim.x + threadIdx.x;
    if (i >= O*Cpad) return;
    int o = i / Cpad, c = i % Cpad;
    float w1 = 0.f, w2 = 0.f;
    if (c < Creal) {
        w1 = W[o*2*Creal + c];
        w2 = W[o*2*Creal + Creal + c];
    }
    Wc[o*Cpad + c]       = w1;
    Wc[(O + o)*Cpad + c] = w2 - w1;
}

__global__ void k_edge_fuse(const float* __restrict__ U, int O,
                            const int* __restrict__ idx,
                            float* __restrict__ HM,
                            float* __restrict__ part1, float* __restrict__ part2)
{
    __shared__ float ss0[256], ss1[256];
    const int ld = 2*O;
    int nsub = 256 / O;
    int o   = threadIdx.x % O;
    int sub = threadIdx.x / O;
    int row0 = blockIdx.x * 16;
    float s0 = 0.f, s1 = 0.f;
    for (int r = row0 + sub; r < row0 + 16; r += nsub) {
        int b = r >> 11;
        float tc = U[(size_t)r*ld + O + o];
        const int* ir = idx + r*KNN;
        float mx = -FLT_MAX, mn = FLT_MAX;
#pragma unroll
        for (int k = 0; k < KNN; ++k) {
            int nb = ir[k];
            float h = U[((size_t)(b << 11) + nb)*ld + o] + tc;
            s0 += h; s1 += h*h;
            mx = fmaxf(mx, h);
            mn = fminf(mn, h);
        }
        HM[(size_t)r*1024 + o]       = mx;
        HM[(size_t)r*1024 + 512 + o] = mn;
    }
    ss0[threadIdx.x] = s0;
    ss1[threadIdx.x] = s1;
    __syncthreads();
    if (threadIdx.x < O) {
        float a = 0.f, b = 0.f;
        for (int s = 0; s < nsub; ++s) {
            a += ss0[s*O + threadIdx.x];
            b += ss1[s*O + threadIdx.x];
        }
        part1[(size_t)blockIdx.x*O + threadIdx.x] = a;
        part2[(size_t)blockIdx.x*O + threadIdx.x] = b;
    }
}

__global__ void k_bn_finalize(const float* __restrict__ gsum, const float* __restrict__ gsq,
                              const float* __restrict__ g, const float* __restrict__ bch,
                              float* __restrict__ scale, float* __restrict__ shift,
                              int O, float invcnt)
{
    int o = blockIdx.x * blockDim.x + threadIdx.x;
    if (o >= O) return;
    float m  = gsum[o] * invcnt;
    float vv = gsq[o] * invcnt - m*m;
    float sc = g[o] / sqrtf(vv + EPSBN);
    scale[o] = sc;
    shift[o] = bch[o] - m*sc;
}

__global__ void k_edge_apply(const float* __restrict__ HM, int O,
                             const float* __restrict__ scale, const float* __restrict__ shift,
                             float* __restrict__ cat, int catoff)
{
    int i = blockIdx.x * blockDim.x + threadIdx.x;
    if (i >= MROWS*O) return;
    int r = i / O, o = i % O;
    float sc = scale[o], sh = shift[o];
    float h = (sc >= 0.f) ? HM[(size_t)r*1024 + o] : HM[(size_t)r*1024 + 512 + o];
    float z = h*sc + sh;
    cat[(size_t)r*512 + catoff + o] = (z >= 0.f) ? z : 0.2f*z;
}

__global__ void k_pool_init(unsigned int* pmax)
{
    int i = blockIdx.x * blockDim.x + threadIdx.x;
    if (i < BQ*1024) pmax[i] = 0u;
}

__global__ void k_pool_part(const float* __restrict__ Y,
                            const float* __restrict__ scale, const float* __restrict__ shift,
                            unsigned int* __restrict__ pmax, float* __restrict__ pchunk)
{
    int b  = blockIdx.x;
    int o  = blockIdx.y * 256 + threadIdx.x;
    int n0 = blockIdx.z * 256;
    float sc = scale[o], sh = shift[o];
    float mx = -FLT_MAX, sm = 0.f;
    for (int n = n0; n < n0 + 256; ++n) {
        float v = Y[((size_t)b*NP + n)*1024 + o]*sc + sh;
        v = (v >= 0.f) ? v : 0.2f*v;
        mx = fmaxf(mx, v);
        sm += v;
    }
    atomicMax(&pmax[b*1024 + o], fenc(mx));
    pchunk[(size_t)blockIdx.z*(BQ*1024) + b*1024 + o] = sm;
}

__global__ void k_pool_fin(const unsigned int* __restrict__ pmax,
                           const float* __restrict__ pchunk, float* __restrict__ P)
{
    int i = blockIdx.x * blockDim.x + threadIdx.x;
    if (i >= BQ*1024) return;
    int b = i >> 10, o = i & 1023;
    float sm = 0.f;
#pragma unroll
    for (int z = 0; z < 8; ++z) sm += pchunk[(size_t)z*(BQ*1024) + i];
    P[b*2048 + o]        = fdec(pmax[i]);
    P[b*2048 + 1024 + o] = sm * (1.f/(float)NP);
}

__global__ void k_fc(const float* __restrict__ In, const float* __restrict__ W,
                     const float* __restrict__ bias, float* __restrict__ Out,
                     int F, int Kd)
{
    int f = blockIdx.x * blockDim.x + threadIdx.x;
    if (f >= F) return;
    float acc[BQ] = {};
    const float* wr = W + (size_t)f*Kd;
    for (int j = 0; j < Kd; ++j) {
        float w = wr[j];
#pragma unroll
        for (int b = 0; b < BQ; ++b) acc[b] += In[b*Kd + j]*w;
    }
    float bb = bias ? bias[f] : 0.f;
#pragma unroll
    for (int b = 0; b < BQ; ++b) Out[b*F + f] = acc[b] + bb;
}

__global__ void k_bn_batch(float* __restrict__ X, const float* __restrict__ g,
                           const float* __restrict__ bch, int F)
{
    int f = blockIdx.x * blockDim.x + threadIdx.x;
    if (f >= F) return;
    float m = 0.f;
#pragma unroll
    for (int b = 0; b < BQ; ++b) m += X[b*F + f];
    m *= (1.f/BQ);
    float vv = 0.f;
#pragma unroll
    for (int b = 0; b < BQ; ++b) { float d = X[b*F + f] - m; vv += d*d; }
    vv *= (1.f/BQ);
    float sc = g[f] / sqrtf(vv + EPSBN);
    float sh = bch[f] - m*sc;
#pragma unroll
    for (int b = 0; b < BQ; ++b) {
        float z = X[b*F + f]*sc + sh;
        X[b*F + f] = (z >= 0.f) ? z : 0.2f*z;
    }
}

// ------------------------------- host side ----------------------------------

struct Ptrs {
    float *XT, *CAT, *U, *Y, *D, *XX, *WC, *P1, *P2, *PCH, *SUM, *SQ, *SC, *SH,
          *P, *H1, *H2;
    unsigned int *PMAX;
    int *IDX;
};

static void run_edge_block(const Ptrs& p,
                           const float* Xact, int ldx, int xoff, int Creal, int Cpad,
                           int O, const float* W, const float* g, const float* bch,
                           int catoff)
{
    k_sqnorm<<<MROWS/256, 256>>>(Xact, ldx, xoff, Creal, p.XX);
    k_dist_sym<<<dim3(136, 1, BQ), 256>>>(Xact, ldx, xoff, p.XX, p.D, Cpad);
    k_topk<<<MROWS/8, 256>>>(p.D, p.IDX);
    k_prepw<<<(O*Cpad + 255)/256, 256>>>(W, p.WC, O, Creal, Cpad);
    k_gemm128<<<dim3((2*O)/128, MROWS/128), 256>>>(Xact, ldx, xoff, p.WC, Cpad, p.U, 2*O, 0, Cpad);
    k_edge_fuse<<<MROWS/16, 256>>>(p.U, O, p.IDX, p.Y, p.P1, p.P2);
    k_stats_reduce<<<(O + 31)/32, 256>>>(p.P1, p.P2, MROWS/16, O, O, p.SUM, p.SQ);
    k_bn_finalize<<<(O + 255)/256, 256>>>(p.SUM, p.SQ, g, bch, p.SC, p.SH, O,
                                          1.f/((float)MROWS*(float)KNN));
    k_edge_apply<<<(MROWS*O + 255)/256, 256>>>(p.Y, O, p.SC, p.SH, p.CAT, catoff);
}

extern "C" void kernel_launch(void* const* d_in, const int* in_sizes, int n_in,
                              void* d_out, int out_size)
{
    const float* x   = (const float*)d_in[0];
    const float* W1  = (const float*)d_in[1];
    const float* g1  = (const float*)d_in[2];
    const float* b1  = (const float*)d_in[3];
    const float* W2  = (const float*)d_in[4];
    const float* g2  = (const float*)d_in[5];
    const float* b2  = (const float*)d_in[6];
    const float* W3  = (const float*)d_in[7];
    const float* g3  = (const float*)d_in[8];
    const float* b3  = (const float*)d_in[9];
    const float* W4  = (const float*)d_in[10];
    const float* g4  = (const float*)d_in[11];
    const float* b4  = (const float*)d_in[12];
    const float* W5  = (const float*)d_in[13];
    const float* g5  = (const float*)d_in[14];
    const float* b5  = (const float*)d_in[15];
    const float* Wl1 = (const float*)d_in[16];
    const float* g6  = (const float*)d_in[17];
    const float* b6  = (const float*)d_in[18];
    const float* Wl2 = (const float*)d_in[19];
    const float* bl2 = (const float*)d_in[20];
    const float* g7  = (const float*)d_in[21];
    const float* b7  = (const float*)d_in[22];
    const float* Wl3 = (const float*)d_in[23];
    const float* bl3 = (const float*)d_in[24];
    (void)in_sizes; (void)n_in;

    Ptrs p;
    cudaGetSymbolAddress((void**)&p.XT,   g_XT);
    cudaGetSymbolAddress((void**)&p.CAT,  g_cat);
    cudaGetSymbolAddress((void**)&p.U,    g_U);
    cudaGetSymbolAddress((void**)&p.Y,    g_Y);
    cudaGetSymbolAddress((void**)&p.D,    g_D);
    cudaGetSymbolAddress((void**)&p.XX,   g_xx);
    cudaGetSymbolAddress((void**)&p.WC,   g_Wc);
    cudaGetSymbolAddress((void**)&p.P1,   g_part1);
    cudaGetSymbolAddress((void**)&p.P2,   g_part2);
    cudaGetSymbolAddress((void**)&p.PCH,  g_pchunk);
    cudaGetSymbolAddress((void**)&p.SUM,  g_sum);
    cudaGetSymbolAddress((void**)&p.SQ,   g_sumsq);
    cudaGetSymbolAddress((void**)&p.SC,   g_scale);
    cudaGetSymbolAddress((void**)&p.SH,   g_shift);
    cudaGetSymbolAddress((void**)&p.P,    g_P);
    cudaGetSymbolAddress((void**)&p.H1,   g_h1);
    cudaGetSymbolAddress((void**)&p.H2,   g_h2);
    cudaGetSymbolAddress((void**)&p.IDX,  g_idx);
    cudaGetSymbolAddress((void**)&p.PMAX, g_pmax);

    k_transpose_pad<<<MROWS/256, 256>>>(x, p.XT);

    run_edge_block(p, p.XT,  16,  0,   3,   16,  64,  W1, g1, b1, 0);
    run_edge_block(p, p.CAT, 512, 0,   64,  64,  64,  W2, g2, b2, 64);
    run_edge_block(p, p.CAT, 512, 64,  64,  64,  128, W3, g3, b3, 128);
    run_edge_block(p, p.CAT, 512, 128, 128, 128, 256, W4, g4, b4, 256);

    // stage 5: Y = cat (16384x512) @ W5^T (1024x512), deterministic fused stats
    k_gemm128s<<<dim3(1024/128, MROWS/128), 256>>>(p.CAT, 512, W5, 512, p.Y, 1024,
                                                   512, p.P1, p.P2);
    k_stats_reduce<<<32, 256>>>(p.P1, p.P2, MROWS/128, 1024, 1024, p.SUM, p.SQ);
    k_bn_finalize<<<4, 256>>>(p.SUM, p.SQ, g5, b5, p.SC, p.SH, 1024, 1.f/(float)MROWS);
    k_pool_init<<<(BQ*1024 + 255)/256, 256>>>(p.PMAX);
    k_pool_part<<<dim3(BQ, 4, NP/256), 256>>>(p.Y, p.SC, p.SH, p.PMAX, p.PCH);
    k_pool_fin<<<(BQ*1024 + 255)/256, 256>>>(p.PMAX, p.PCH, p.P);

    // FC head
    k_fc<<<2, 256>>>(p.P,  Wl1, nullptr, p.H1, 512, 2048);
    k_bn_batch<<<2, 256>>>(p.H1, g6, b6, 512);
    k_fc<<<1, 256>>>(p.H1, Wl2, bl2,     p.H2, 256, 512);
    k_bn_batch<<<1, 256>>>(p.H2, g7, b7, 256);
    k_fc<<<1, 64>>>(p.H2, Wl3, bl3, (float*)d_out, 40, 256);
}

// round 15
// speedup vs baseline: 1.0562x; 1.0562x over previous
#include <cuda_runtime.h>
#include <cuda_bf16.h>
#include <float.h>
#include <stdint.h>

#define BQ 8
#define NP 2048
#define KNN 20
#define MROWS (BQ*NP)        // 16384
#define EPSBN 1e-5f
#define TCAP 192
#define LDT 136

// ------------------------- device scratch (global) --------------------------
__device__ float g_XT[MROWS*16];
__device__ float g_cat[(size_t)MROWS*512];
__device__ float g_U[(size_t)MROWS*512];
__device__ float g_Y[(size_t)MROWS*1024];
__device__ float g_D[(size_t)MROWS*NP];
__device__ float g_xx[MROWS];
__device__ int   g_idx[MROWS*KNN];
__device__ float g_Wc[512*512];
__device__ float g_part1[1024*1024];
__device__ float g_part2[1024*1024];
__device__ float g_pchunk[8*BQ*1024];
__device__ float g_sum[1024];
__device__ float g_sumsq[1024];
__device__ float g_scale[1024];
__device__ float g_shift[1024];
__device__ float g_P[BQ*2048];
__device__ float g_h1[BQ*512];
__device__ float g_h2[BQ*256];
__device__ unsigned int g_pmax[BQ*1024];

// ------------------------------ helpers -------------------------------------

__device__ __forceinline__ unsigned int fenc(float v) {
    unsigned int b = __float_as_uint(v);
    return (b & 0x80000000u) ? ~b : (b | 0x80000000u);
}
__device__ __forceinline__ float fdec(unsigned int u) {
    unsigned int b = (u & 0x80000000u) ? (u ^ 0x80000000u) : ~u;
    return __uint_as_float(b);
}

__device__ __forceinline__ void tile_store(float* S, int f, float4 v)
{
    int m  = f >> 2;
    int kq = f & 3;
    int col = m ^ (kq << 3);
    S[(4*kq + 0)*128 + col] = v.x;
    S[(4*kq + 1)*128 + col] = v.y;
    S[(4*kq + 2)*128 + col] = v.z;
    S[(4*kq + 3)*128 + col] = v.w;
}

__device__ __forceinline__ float f2tf(float x) {
    unsigned y; asm("cvt.rna.tf32.f32 %0, %1;" : "=r"(y) : "f"(x));
    return __uint_as_float(y);
}
__device__ __forceinline__ void mma_tf32(float* c,
    float a0, float a1, float a2, float a3, float b0, float b1)
{
    asm volatile(
        "mma.sync.aligned.m16n8k8.row.col.f32.tf32.tf32.f32 "
        "{%0,%1,%2,%3}, {%4,%5,%6,%7}, {%8,%9}, {%0,%1,%2,%3};"
        : "+f"(c[0]), "+f"(c[1]), "+f"(c[2]), "+f"(c[3])
        : "r"(__float_as_uint(a0)), "r"(__float_as_uint(a1)),
          "r"(__float_as_uint(a2)), "r"(__float_as_uint(a3)),
          "r"(__float_as_uint(b0)), "r"(__float_as_uint(b1)));
}

// ------------------------------- kernels ------------------------------------

__global__ void k_transpose_pad(const float* __restrict__ x, float* __restrict__ XT)
{
    int i = blockIdx.x * blockDim.x + threadIdx.x;
    if (i >= MROWS) return;
    int b = i >> 11, n = i & (NP-1);
    float v0 = x[(b*3 + 0)*NP + n];
    float v1 = x[(b*3 + 1)*NP + n];
    float v2 = x[(b*3 + 2)*NP + n];
    float4* o = (float4*)(XT + (size_t)i*16);
    o[0] = make_float4(v0, v1, v2, 0.f);
    o[1] = make_float4(0.f, 0.f, 0.f, 0.f);
    o[2] = make_float4(0.f, 0.f, 0.f, 0.f);
    o[3] = make_float4(0.f, 0.f, 0.f, 0.f);
}

__global__ void k_sqnorm(const float* __restrict__ X, int ldx, int xoff, int C,
                         float* __restrict__ xx)
{
    int r = blockIdx.x * blockDim.x + threadIdx.x;
    if (r >= MROWS) return;
    const float* p = X + (size_t)r*ldx + xoff;
    float s = 0.f;
    for (int c = 0; c < C; ++c) { float v = p[c]; s += v*v; }
    xx[r] = s;
}

// Symmetric pairwise distance: upper-tri tiles + direct mirror (R11 version)
__global__ void __launch_bounds__(256, 2)
k_dist_sym(const float* __restrict__ X, int ldx, int xoff,
           const float* __restrict__ xx, float* __restrict__ D, int Kd)
{
    __shared__ float As[16*128];
    __shared__ float Bs[16*128];
    int b = blockIdx.z;
    int li = blockIdx.x;
    int ti = 0;
    while (li >= 16 - ti) { li -= 16 - ti; ++ti; }
    int tj = ti + li;
    int n0 = ti * 128;
    int m0 = tj * 128;
    size_t base = (size_t)b * NP;
    int t  = threadIdx.x;
    int tx = t & 15, ty = t >> 4;

    float acc[8][8] = {};
    int f0 = t, f1 = t + 256;
    float4 pa0 = *(const float4*)(X + (base + n0 + (f0>>2))*(size_t)ldx + xoff + (f0&3)*4);
    float4 pa1 = *(const float4*)(X + (base + n0 + (f1>>2))*(size_t)ldx + xoff + (f1&3)*4);
    float4 pb0 = *(const float4*)(X + (base + m0 + (f0>>2))*(size_t)ldx + xoff + (f0&3)*4);
    float4 pb1 = *(const float4*)(X + (base + m0 + (f1>>2))*(size_t)ldx + xoff + (f1&3)*4);

    for (int k0 = 0; k0 < Kd; k0 += 16) {
        tile_store(As, f0, pa0);
        tile_store(As, f1, pa1);
        tile_store(Bs, f0, pb0);
        tile_store(Bs, f1, pb1);
        __syncthreads();
        if (k0 + 16 < Kd) {
            int kn = k0 + 16;
            pa0 = *(const float4*)(X + (base + n0 + (f0>>2))*(size_t)ldx + xoff + kn + (f0&3)*4);
            pa1 = *(const float4*)(X + (base + n0 + (f1>>2))*(size_t)ldx + xoff + kn + (f1&3)*4);
            pb0 = *(const float4*)(X + (base + m0 + (f0>>2))*(size_t)ldx + xoff + kn + (f0&3)*4);
            pb1 = *(const float4*)(X + (base + m0 + (f1>>2))*(size_t)ldx + xoff + kn + (f1&3)*4);
        }
#pragma unroll
        for (int kk = 0; kk < 16; ++kk) {
            int swz = (kk >> 2) << 3;
            const float4* pa = (const float4*)&As[kk*128 + ((ty*8) ^ swz)];
            const float4* pb = (const float4*)&Bs[kk*128 + ((tx*8) ^ swz)];
            float4 a03 = pa[0], a47 = pa[1];
            float4 b03 = pb[0], b47 = pb[1];
            float a_[8] = {a03.x,a03.y,a03.z,a03.w,a47.x,a47.y,a47.z,a47.w};
            float b_[8] = {b03.x,b03.y,b03.z,b03.w,b47.x,b47.y,b47.z,b47.w};
#pragma unroll
            for (int i = 0; i < 8; ++i)
#pragma unroll
                for (int j = 0; j < 8; ++j) acc[i][j] += a_[i]*b_[j];
        }
        __syncthreads();
    }
    float xm[8];
#pragma unroll
    for (int j = 0; j < 8; ++j) xm[j] = xx[base + m0 + tx*8 + j];
#pragma unroll
    for (int i = 0; i < 8; ++i) {
        float xn = xx[base + n0 + ty*8 + i];
#pragma unroll
        for (int j = 0; j < 8; ++j) acc[i][j] = 2.f*acc[i][j] - xn - xm[j];
    }
#pragma unroll
    for (int i = 0; i < 8; ++i) {
        float* dp = D + (base + n0 + ty*8 + i)*(size_t)NP + m0 + tx*8;
        ((float4*)dp)[0] = make_float4(acc[i][0], acc[i][1], acc[i][2], acc[i][3]);
        ((float4*)dp)[1] = make_float4(acc[i][4], acc[i][5], acc[i][6], acc[i][7]);
    }
    if (m0 != n0) {
#pragma unroll
        for (int j = 0; j < 8; ++j) {
            float* dp = D + (base + m0 + tx*8 + j)*(size_t)NP + n0 + ty*8;
            ((float4*)dp)[0] = make_float4(acc[0][j], acc[1][j], acc[2][j], acc[3][j]);
            ((float4*)dp)[1] = make_float4(acc[4][j], acc[5][j], acc[6][j], acc[7][j]);
        }
    }
}

// ---- warp top-20 (R11): lane-max bound pass, then single filtered collect ----
__global__ void __launch_bounds__(256)
k_topk(const float* __restrict__ D, int* __restrict__ idxout)
{
    __shared__ unsigned long long sbuf[8][TCAP];
    __shared__ unsigned long long slist[8][KNN];
    __shared__ int scnt[8];

    int warp = threadIdx.x >> 5, lane = threadIdx.x & 31;
    int row  = blockIdx.x * 8 + warp;
    const float4* drow4 = (const float4*)(D + (size_t)row * NP);

    float lmax = -FLT_MAX;
#pragma unroll
    for (int f = 0; f < 16; ++f) {
        float4 v4 = drow4[f*32 + lane];
        lmax = fmaxf(lmax, fmaxf(fmaxf(v4.x, v4.y), fmaxf(v4.z, v4.w)));
    }
    int rank = 0;
#pragma unroll
    for (int i = 0; i < 32; ++i) {
        float vi = __shfl_sync(0xffffffffu, lmax, i);
        rank += (vi > lmax || (vi == lmax && i < lane)) ? 1 : 0;
    }
    unsigned r19 = __ballot_sync(0xffffffffu, rank == 19);
    float T = __shfl_sync(0xffffffffu, lmax, __ffs(r19) - 1);

    if (lane == 0) scnt[warp] = 0;
    __syncwarp();

#pragma unroll 4
    for (int f = 0; f < 16; ++f) {
        float4 v4 = drow4[f*32 + lane];
        int base = (f*32 + lane)*4;
        unsigned q = 0;
        q |= (v4.x >= T) ? 1u : 0u;
        q |= (v4.y >= T) ? 2u : 0u;
        q |= (v4.z >= T) ? 4u : 0u;
        q |= (v4.w >= T) ? 8u : 0u;
        if (q) {
            float vals[4] = {v4.x, v4.y, v4.z, v4.w};
#pragma unroll 1
            do {
                int e = __ffs(q) - 1;
                q &= q - 1;
                int pos = atomicAdd(&scnt[warp], 1);
                if (pos < TCAP)
                    sbuf[warp][pos] =
                        (((unsigned long long)fenc(vals[e])) << 32)
                        | (unsigned)(NP - 1 - (base + e));
            } while (q);
        }
    }
    __syncwarp();

    if (lane == 0) {
        unsigned long long* L = slist[warp];
#pragma unroll
        for (int i = 0; i < KNN; ++i) L[i] = 0ull;
        int c = scnt[warp];
        if (c <= TCAP) {
            for (int i = 0; i < c; ++i) {
                unsigned long long key = sbuf[warp][i];
                if (key > L[KNN-1]) {
                    int qq = KNN-1;
#pragma unroll 1
                    while (qq > 0 && L[qq-1] < key) { L[qq] = L[qq-1]; --qq; }
                    L[qq] = key;
                }
            }
        } else {
            const float* drow = (const float*)drow4;
            for (int mI = 0; mI < NP; ++mI) {
                unsigned long long key =
                    (((unsigned long long)fenc(drow[mI])) << 32)
                    | (unsigned)(NP - 1 - mI);
                if (key > L[KNN-1]) {
                    int qq = KNN-1;
#pragma unroll 1
                    while (qq > 0 && L[qq-1] < key) { L[qq] = L[qq-1]; --qq; }
                    L[qq] = key;
                }
            }
        }
    }
    __syncwarp();
    if (lane < KNN) {
        unsigned long long key = slist[warp][lane];
        idxout[row*KNN + lane] = NP - 1 - (int)(key & 0xffffffffu);
    }
}

// ---- 128x128x16 fp32 GEMM (conv blocks) ----
__global__ void __launch_bounds__(256, 2)
k_gemm128(const float* __restrict__ A, int lda, int aoff,
          const float* __restrict__ Bw, int ldb,
          float* __restrict__ Cm, int ldc, int coff,
          int Kd)
{
    __shared__ float As[16*128];
    __shared__ float Bs[16*128];
    int n0 = blockIdx.x * 128;
    int m0 = blockIdx.y * 128;
    int t  = threadIdx.x;
    int tx = t & 15, ty = t >> 4;

    float acc[8][8] = {};
    int f0 = t, f1 = t + 256;
    float4 pa0 = *(const float4*)(A  + (size_t)(m0 + (f0>>2))*lda + aoff + (f0&3)*4);
    float4 pa1 = *(const float4*)(A  + (size_t)(m0 + (f1>>2))*lda + aoff + (f1&3)*4);
    float4 pb0 = *(const float4*)(Bw + (size_t)(n0 + (f0>>2))*ldb + (f0&3)*4);
    float4 pb1 = *(const float4*)(Bw + (size_t)(n0 + (f1>>2))*ldb + (f1&3)*4);

    for (int k0 = 0; k0 < Kd; k0 += 16) {
        tile_store(As, f0, pa0);
        tile_store(As, f1, pa1);
        tile_store(Bs, f0, pb0);
        tile_store(Bs, f1, pb1);
        __syncthreads();
        if (k0 + 16 < Kd) {
            int kn = k0 + 16;
            pa0 = *(const float4*)(A  + (size_t)(m0 + (f0>>2))*lda + aoff + kn + (f0&3)*4);
            pa1 = *(const float4*)(A  + (size_t)(m0 + (f1>>2))*lda + aoff + kn + (f1&3)*4);
            pb0 = *(const float4*)(Bw + (size_t)(n0 + (f0>>2))*ldb + kn + (f0&3)*4);
            pb1 = *(const float4*)(Bw + (size_t)(n0 + (f1>>2))*ldb + kn + (f1&3)*4);
        }
#pragma unroll
        for (int kk = 0; kk < 16; ++kk) {
            int swz = (kk >> 2) << 3;
            const float4* pa = (const float4*)&As[kk*128 + ((ty*8) ^ swz)];
            const float4* pb = (const float4*)&Bs[kk*128 + ((tx*8) ^ swz)];
            float4 a03 = pa[0], a47 = pa[1];
            float4 b03 = pb[0], b47 = pb[1];
            float a_[8] = {a03.x,a03.y,a03.z,a03.w,a47.x,a47.y,a47.z,a47.w};
            float b_[8] = {b03.x,b03.y,b03.z,b03.w,b47.x,b47.y,b47.z,b47.w};
#pragma unroll
            for (int i = 0; i < 8; ++i)
#pragma unroll
                for (int j = 0; j < 8; ++j) acc[i][j] += a_[i]*b_[j];
        }
        __syncthreads();
    }
#pragma unroll
    for (int i = 0; i < 8; ++i) {
        float* cp = Cm + (size_t)(m0 + ty*8 + i)*ldc + coff + n0 + tx*8;
        ((float4*)cp)[0] = make_float4(acc[i][0], acc[i][1], acc[i][2], acc[i][3]);
        ((float4*)cp)[1] = make_float4(acc[i][4], acc[i][5], acc[i][6], acc[i][7]);
    }
}

// ---- stage-5: 3xTF32 mma with pre-split smem (convert once at store) ----
// block 128x128, BK=8, 8 warps (2x4), warp 64x32; deterministic stats epilogue.
__global__ void __launch_bounds__(256, 2)
k_gemm_tf32s(const float* __restrict__ A, int lda,
             const float* __restrict__ Bw, int ldb,
             float* __restrict__ Cm, int ldc,
             int Kd, float* __restrict__ part1, float* __restrict__ part2)
{
    __shared__ float Ah[8*LDT], Al[8*LDT], Bh[8*LDT], Bl[8*LDT];
    int n0 = blockIdx.x * 128;
    int m0 = blockIdx.y * 128;
    int t = threadIdx.x;
    int warp = t >> 5, lane = t & 31;
    int wm = warp >> 2, wn = warp & 3;
    int g = lane >> 2, q = lane & 3;

    float acc[4][4][4];
#pragma unroll
    for (int a = 0; a < 4; ++a)
#pragma unroll
        for (int b = 0; b < 4; ++b)
#pragma unroll
            for (int c = 0; c < 4; ++c) acc[a][b][c] = 0.f;

    int lm = t >> 1, lh = (t & 1) * 4;   // row within tile, k-quad
    float4 va = *(const float4*)(A  + (size_t)(m0 + lm)*lda + lh);
    float4 vb = *(const float4*)(Bw + (size_t)(n0 + lm)*ldb + lh);

    for (int k0 = 0; k0 < Kd; k0 += 8) {
        {
            float av[4] = {va.x, va.y, va.z, va.w};
            float bv[4] = {vb.x, vb.y, vb.z, vb.w};
#pragma unroll
            for (int j = 0; j < 4; ++j) {
                float hi = f2tf(av[j]);
                Ah[(lh + j)*LDT + lm] = hi;
                Al[(lh + j)*LDT + lm] = f2tf(av[j] - hi);
                float hib = f2tf(bv[j]);
                Bh[(lh + j)*LDT + lm] = hib;
                Bl[(lh + j)*LDT + lm] = f2tf(bv[j] - hib);
            }
        }
        __syncthreads();
        if (k0 + 8 < Kd) {
            int kn = k0 + 8;
            va = *(const float4*)(A  + (size_t)(m0 + lm)*lda + kn + lh);
            vb = *(const float4*)(Bw + (size_t)(n0 + lm)*ldb + kn + lh);
        }
        // B fragments
        float bh0[4], bh1[4], bl0[4], bl1[4];
#pragma unroll
        for (int nt = 0; nt < 4; ++nt) {
            int nn = wn*32 + nt*8 + g;
            bh0[nt] = Bh[q*LDT + nn];
            bh1[nt] = Bh[(q+4)*LDT + nn];
            bl0[nt] = Bl[q*LDT + nn];
            bl1[nt] = Bl[(q+4)*LDT + nn];
        }
#pragma unroll
        for (int mt = 0; mt < 4; ++mt) {
            int mm = wm*64 + mt*16 + g;
            float ah0 = Ah[q*LDT + mm],     ah1 = Ah[q*LDT + mm + 8];
            float ah2 = Ah[(q+4)*LDT + mm], ah3 = Ah[(q+4)*LDT + mm + 8];
            float al0 = Al[q*LDT + mm],     al1 = Al[q*LDT + mm + 8];
            float al2 = Al[(q+4)*LDT + mm], al3 = Al[(q+4)*LDT + mm + 8];
#pragma unroll
            for (int nt = 0; nt < 4; ++nt) {
                mma_tf32(acc[mt][nt], ah0, ah1, ah2, ah3, bh0[nt], bh1[nt]);
                mma_tf32(acc[mt][nt], al0, al1, al2, al3, bh0[nt], bh1[nt]);
                mma_tf32(acc[mt][nt], ah0, ah1, ah2, ah3, bl0[nt], bl1[nt]);
            }
        }
        __syncthreads();
    }

    // write C: thread holds rows {r, r+8}, cols {2q, 2q+1}
#pragma unroll
    for (int mt = 0; mt < 4; ++mt) {
        int r = m0 + wm*64 + mt*16 + g;
#pragma unroll
        for (int nt = 0; nt < 4; ++nt) {
            int c = n0 + wn*32 + nt*8 + 2*q;
            *(float2*)(Cm + (size_t)r*ldc + c)     = make_float2(acc[mt][nt][0], acc[mt][nt][1]);
            *(float2*)(Cm + (size_t)(r+8)*ldc + c) = make_float2(acc[mt][nt][2], acc[mt][nt][3]);
        }
    }

    // deterministic per-column partial stats over this warp's 64 rows
#pragma unroll
    for (int nt = 0; nt < 4; ++nt) {
        float s0 = 0.f, s1 = 0.f, q0 = 0.f, q1 = 0.f;
#pragma unroll
        for (int mt = 0; mt < 4; ++mt) {
            float e0 = acc[mt][nt][0], e1 = acc[mt][nt][1];
            float e2 = acc[mt][nt][2], e3 = acc[mt][nt][3];
            s0 += e0 + e2;  q0 += e0*e0 + e2*e2;
            s1 += e1 + e3;  q1 += e1*e1 + e3*e3;
        }
#pragma unroll
        for (int sft = 4; sft < 32; sft <<= 1) {
            s0 += __shfl_xor_sync(0xffffffffu, s0, sft);
            s1 += __shfl_xor_sync(0xffffffffu, s1, sft);
            q0 += __shfl_xor_sync(0xffffffffu, q0, sft);
            q1 += __shfl_xor_sync(0xffffffffu, q1, sft);
        }
        if (g == 0) {
            size_t slot = ((size_t)blockIdx.y*2 + wm)*1024;
            int c = n0 + wn*32 + nt*8 + 2*q;
            part1[slot + c]     = s0;
            part2[slot + c]     = q0;
            part1[slot + c + 1] = s1;
            part2[slot + c + 1] = q1;
        }
    }
}

// deterministic parallel reduction of partials: part[s*stride + o]
__global__ void k_stats_reduce(const float* __restrict__ part1,
                               const float* __restrict__ part2,
                               int nparts, int stride, int O,
                               float* __restrict__ gsum, float* __restrict__ gsq)
{
    __shared__ float s1[8][32], s2[8][32];
    int lane = threadIdx.x & 31;
    int sl   = threadIdx.x >> 5;
    int o    = blockIdx.x * 32 + lane;
    int per  = nparts >> 3;
    float a = 0.f, b = 0.f;
    if (o < O) {
        for (int s = sl*per; s < (sl+1)*per; ++s) {
            a += part1[(size_t)s*stride + o];
            b += part2[(size_t)s*stride + o];
        }
    }
    s1[sl][lane] = a;
    s2[sl][lane] = b;
    __syncthreads();
    if (sl == 0 && o < O) {
        float A = 0.f, B = 0.f;
#pragma unroll
        for (int s = 0; s < 8; ++s) { A += s1[s][lane]; B += s2[s][lane]; }
        gsum[o] = A;
        gsq[o]  = B;
    }
}

__global__ void k_prepw(const float* __restrict__ W, float* __restrict__ Wc,
                        int O, int Creal, int Cpad)
{
    int i = blockIdx.x * blockDim.x + threadIdx.x;
    if (i >= O*Cpad) return;
    int o = i / Cpad, c = i % Cpad;
    float w1 = 0.f, w2 = 0.f;
    if (c < Creal) {
        w1 = W[o*2*Creal + c];
        w2 = W[o*2*Creal + Creal + c];
    }
    Wc[o*Cpad + c]       = w1;
    Wc[(O + o)*Cpad + c] = w2 - w1;
}

__global__ void k_edge_fuse(const float* __restrict__ U, int O,
                            const int* __restrict__ idx,
                            float* __restrict__ HM,
                            float* __restrict__ part1, float* __restrict__ part2)
{
    __shared__ float ss0[256], ss1[256];
    const int ld = 2*O;
    int nsub = 256 / O;
    int o   = threadIdx.x % O;
    int sub = threadIdx.x / O;
    int row0 = blockIdx.x * 16;
    float s0 = 0.f, s1 = 0.f;
    for (int r = row0 + sub; r < row0 + 16; r += nsub) {
        int b = r >> 11;
        float tc = U[(size_t)r*ld + O + o];
        const int* ir = idx + r*KNN;
        float mx = -FLT_MAX, mn = FLT_MAX;
#pragma unroll
        for (int k = 0; k < KNN; ++k) {
            int nb = ir[k];
            float h = U[((size_t)(b << 11) + nb)*ld + o] + tc;
            s0 += h; s1 += h*h;
            mx = fmaxf(mx, h);
            mn = fminf(mn, h);
        }
        HM[(size_t)r*1024 + o]       = mx;
        HM[(size_t)r*1024 + 512 + o] = mn;
    }
    ss0[threadIdx.x] = s0;
    ss1[threadIdx.x] = s1;
    __syncthreads();
    if (threadIdx.x < O) {
        float a = 0.f, b = 0.f;
        for (int s = 0; s < nsub; ++s) {
            a += ss0[s*O + threadIdx.x];
            b += ss1[s*O + threadIdx.x];
        }
        part1[(size_t)blockIdx.x*O + threadIdx.x] = a;
        part2[(size_t)blockIdx.x*O + threadIdx.x] = b;
    }
}

__global__ void k_bn_finalize(const float* __restrict__ gsum, const float* __restrict__ gsq,
                              const float* __restrict__ g, const float* __restrict__ bch,
                              float* __restrict__ scale, float* __restrict__ shift,
                              int O, float invcnt)
{
    int o = blockIdx.x * blockDim.x + threadIdx.x;
    if (o >= O) return;
    float m  = gsum[o] * invcnt;
    float vv = gsq[o] * invcnt - m*m;
    float sc = g[o] / sqrtf(vv + EPSBN);
    scale[o] = sc;
    shift[o] = bch[o] - m*sc;
}

__global__ void k_edge_apply(const float* __restrict__ HM, int O,
                             const float* __restrict__ scale, const float* __restrict__ shift,
                             float* __restrict__ cat, int catoff)
{
    int i = blockIdx.x * blockDim.x + threadIdx.x;
    if (i >= MROWS*O) return;
    int r = i / O, o = i % O;
    float sc = scale[o], sh = shift[o];
    float h = (sc >= 0.f) ? HM[(size_t)r*1024 + o] : HM[(size_t)r*1024 + 512 + o];
    float z = h*sc + sh;
    cat[(size_t)r*512 + catoff + o] = (z >= 0.f) ? z : 0.2f*z;
}

__global__ void k_pool_init(unsigned int* pmax)
{
    int i = blockIdx.x * blockDim.x + threadIdx.x;
    if (i < BQ*1024) pmax[i] = 0u;
}

__global__ void k_pool_part(const float* __restrict__ Y,
                            const float* __restrict__ scale, const float* __restrict__ shift,
                            unsigned int* __restrict__ pmax, float* __restrict__ pchunk)
{
    int b  = blockIdx.x;
    int o  = blockIdx.y * 256 + threadIdx.x;
    int n0 = blockIdx.z * 256;
    float sc = scale[o], sh = shift[o];
    float mx = -FLT_MAX, sm = 0.f;
    for (int n = n0; n < n0 + 256; ++n) {
        float v = Y[((size_t)b*NP + n)*1024 + o]*sc + sh;
        v = (v >= 0.f) ? v : 0.2f*v;
        mx = fmaxf(mx, v);
        sm += v;
    }
    atomicMax(&pmax[b*1024 + o], fenc(mx));
    pchunk[(size_t)blockIdx.z*(BQ*1024) + b*1024 + o] = sm;
}

__global__ void k_pool_fin(const unsigned int* __restrict__ pmax,
                           const float* __restrict__ pchunk, float* __restrict__ P)
{
    int i = blockIdx.x * blockDim.x + threadIdx.x;
    if (i >= BQ*1024) return;
    int b = i >> 10, o = i & 1023;
    float sm = 0.f;
#pragma unroll
    for (int z = 0; z < 8; ++z) sm += pchunk[(size_t)z*(BQ*1024) + i];
    P[b*2048 + o]        = fdec(pmax[i]);
    P[b*2048 + 1024 + o] = sm * (1.f/(float)NP);
}

__global__ void k_fc(const float* __restrict__ In, const float* __restrict__ W,
                     const float* __restrict__ bias, float* __restrict__ Out,
                     int F, int Kd)
{
    int f = blockIdx.x * blockDim.x + threadIdx.x;
    if (f >= F) return;
    float acc[BQ] = {};
    const float* wr = W + (size_t)f*Kd;
    for (int j = 0; j < Kd; ++j) {
        float w = wr[j];
#pragma unroll
        for (int b = 0; b < BQ; ++b) acc[b] += In[b*Kd + j]*w;
    }
    float bb = bias ? bias[f] : 0.f;
#pragma unroll
    for (int b = 0; b < BQ; ++b) Out[b*F + f] = acc[b] + bb;
}

__global__ void k_bn_batch(float* __restrict__ X, const float* __restrict__ g,
                           const float* __restrict__ bch, int F)
{
    int f = blockIdx.x * blockDim.x + threadIdx.x;
    if (f >= F) return;
    float m = 0.f;
#pragma unroll
    for (int b = 0; b < BQ; ++b) m += X[b*F + f];
    m *= (1.f/BQ);
    float vv = 0.f;
#pragma unroll
    for (int b = 0; b < BQ; ++b) { float d = X[b*F + f] - m; vv += d*d; }
    vv *= (1.f/BQ);
    float sc = g[f] / sqrtf(vv + EPSBN);
    float sh = bch[f] - m*sc;
#pragma unroll
    for (int b = 0; b < BQ; ++b) {
        float z = X[b*F + f]*sc + sh;
        X[b*F + f] = (z >= 0.f) ? z : 0.2f*z;
    }
}

// ------------------------------- host side ----------------------------------

struct Ptrs {
    float *XT, *CAT, *U, *Y, *D, *XX, *WC, *P1, *P2, *PCH, *SUM, *SQ, *SC, *SH,
          *P, *H1, *H2;
    unsigned int *PMAX;
    int *IDX;
};

static void run_edge_block(const Ptrs& p,
                           const float* Xact, int ldx, int xoff, int Creal, int Cpad,
                           int O, const float* W, const float* g, const float* bch,
                           int catoff)
{
    k_sqnorm<<<MROWS/256, 256>>>(Xact, ldx, xoff, Creal, p.XX);
    k_dist_sym<<<dim3(136, 1, BQ), 256>>>(Xact, ldx, xoff, p.XX, p.D, Cpad);
    k_topk<<<MROWS/8, 256>>>(p.D, p.IDX);
    k_prepw<<<(O*Cpad + 255)/256, 256>>>(W, p.WC, O, Creal, Cpad);
    k_gemm128<<<dim3((2*O)/128, MROWS/128), 256>>>(Xact, ldx, xoff, p.WC, Cpad, p.U, 2*O, 0, Cpad);
    k_edge_fuse<<<MROWS/16, 256>>>(p.U, O, p.IDX, p.Y, p.P1, p.P2);
    k_stats_reduce<<<(O + 31)/32, 256>>>(p.P1, p.P2, MROWS/16, O, O, p.SUM, p.SQ);
    k_bn_finalize<<<(O + 255)/256, 256>>>(p.SUM, p.SQ, g, bch, p.SC, p.SH, O,
                                          1.f/((float)MROWS*(float)KNN));
    k_edge_apply<<<(MROWS*O + 255)/256, 256>>>(p.Y, O, p.SC, p.SH, p.CAT, catoff);
}

extern "C" void kernel_launch(void* const* d_in, const int* in_sizes, int n_in,
                              void* d_out, int out_size)
{
    const float* x   = (const float*)d_in[0];
    const float* W1  = (const float*)d_in[1];
    const float* g1  = (const float*)d_in[2];
    const float* b1  = (const float*)d_in[3];
    const float* W2  = (const float*)d_in[4];
    const float* g2  = (const float*)d_in[5];
    const float* b2  = (const float*)d_in[6];
    const float* W3  = (const float*)d_in[7];
    const float* g3  = (const float*)d_in[8];
    const float* b3  = (const float*)d_in[9];
    const float* W4  = (const float*)d_in[10];
    const float* g4  = (const float*)d_in[11];
    const float* b4  = (const float*)d_in[12];
    const float* W5  = (const float*)d_in[13];
    const float* g5  = (const float*)d_in[14];
    const float* b5  = (const float*)d_in[15];
    const float* Wl1 = (const float*)d_in[16];
    const float* g6  = (const float*)d_in[17];
    const float* b6  = (const float*)d_in[18];
    const float* Wl2 = (const float*)d_in[19];
    const float* bl2 = (const float*)d_in[20];
    const float* g7  = (const float*)d_in[21];
    const float* b7  = (const float*)d_in[22];
    const float* Wl3 = (const float*)d_in[23];
    const float* bl3 = (const float*)d_in[24];
    (void)in_sizes; (void)n_in;

    Ptrs p;
    cudaGetSymbolAddress((void**)&p.XT,   g_XT);
    cudaGetSymbolAddress((void**)&p.CAT,  g_cat);
    cudaGetSymbolAddress((void**)&p.U,    g_U);
    cudaGetSymbolAddress((void**)&p.Y,    g_Y);
    cudaGetSymbolAddress((void**)&p.D,    g_D);
    cudaGetSymbolAddress((void**)&p.XX,   g_xx);
    cudaGetSymbolAddress((void**)&p.WC,   g_Wc);
    cudaGetSymbolAddress((void**)&p.P1,   g_part1);
    cudaGetSymbolAddress((void**)&p.P2,   g_part2);
    cudaGetSymbolAddress((void**)&p.PCH,  g_pchunk);
    cudaGetSymbolAddress((void**)&p.SUM,  g_sum);
    cudaGetSymbolAddress((void**)&p.SQ,   g_sumsq);
    cudaGetSymbolAddress((void**)&p.SC,   g_scale);
    cudaGetSymbolAddress((void**)&p.SH,   g_shift);
    cudaGetSymbolAddress((void**)&p.P,    g_P);
    cudaGetSymbolAddress((void**)&p.H1,   g_h1);
    cudaGetSymbolAddress((void**)&p.H2,   g_h2);
    cudaGetSymbolAddress((void**)&p.IDX,  g_idx);
    cudaGetSymbolAddress((void**)&p.PMAX, g_pmax);

    k_transpose_pad<<<MROWS/256, 256>>>(x, p.XT);

    run_edge_block(p, p.XT,  16,  0,   3,   16,  64,  W1, g1, b1, 0);
    run_edge_block(p, p.CAT, 512, 0,   64,  64,  64,  W2, g2, b2, 64);
    run_edge_block(p, p.CAT, 512, 64,  64,  64,  128, W3, g3, b3, 128);
    run_edge_block(p, p.CAT, 512, 128, 128, 128, 256, W4, g4, b4, 256);

    // stage 5: Y = cat (16384x512) @ W5^T (1024x512) via pre-split 3xTF32 mma
    k_gemm_tf32s<<<dim3(1024/128, MROWS/128), 256>>>(p.CAT, 512, W5, 512, p.Y, 1024,
                                                     512, p.P1, p.P2);
    k_stats_reduce<<<32, 256>>>(p.P1, p.P2, 2*(MROWS/128), 1024, 1024, p.SUM, p.SQ);
    k_bn_finalize<<<4, 256>>>(p.SUM, p.SQ, g5, b5, p.SC, p.SH, 1024, 1.f/(float)MROWS);
    k_pool_init<<<(BQ*1024 + 255)/256, 256>>>(p.PMAX);
    k_pool_part<<<dim3(BQ, 4, NP/256), 256>>>(p.Y, p.SC, p.SH, p.PMAX, p.PCH);
    k_pool_fin<<<(BQ*1024 + 255)/256, 256>>>(p.PMAX, p.PCH, p.P);

    // FC head
    k_fc<<<2, 256>>>(p.P,  Wl1, nullptr, p.H1, 512, 2048);
    k_bn_batch<<<2, 256>>>(p.H1, g6, b6, 512);
    k_fc<<<1, 256>>>(p.H1, Wl2, bl2,     p.H2, 256, 512);
    k_bn_batch<<<1, 256>>>(p.H2, g7, b7, 256);
    k_fc<<<1, 64>>>(p.H2, Wl3, bl3, (float*)d_out, 40, 256);
}